// round 3
// baseline (speedup 1.0000x reference)
#include <cuda_runtime.h>
#include <math.h>

// Problem constants (fixed by the dataset)
#define Ec     3072   // edges = K*DV
#define Kv     1024   // variable nodes
#define Nc     512    // check nodes
#define Bb     2048   // batch
#define MAXDEG 32     // max check-node degree bound (Poisson(6); P(>32) ~ 1e-15)
#define MAXNB  32
#define CLIPV  10.0f
#define TPB    512

// ---------------- persistent scratch (__device__ globals; no allocs) ----------------
__device__ int   g_chk[Ec];
__device__ int   g_var[Ec];
__device__ int   g_cdeg[Nc];
__device__ int   g_cadj[Nc * MAXDEG];
__device__ int   g_sib0[Ec];
__device__ int   g_sib1[Ec];
__device__ int   g_nnb[Ec];
__device__ int   g_nbr[MAXNB * Ec];      // [j*Ec + e] SoA for coalescing
__device__ float g_w1 [MAXNB * Ec];
__device__ float g_w2 [MAXNB * Ec];
__device__ float g_w3 [MAXNB * Ec];
__device__ float g_wo [Ec];

// ---------------- setup 1: recover chk[e], var[e] from the one-hot masks ----------------
__global__ void k_struct(const float* __restrict__ in_mask,
                         const float* __restrict__ out_mask) {
    int e = blockIdx.x * blockDim.x + threadIdx.x;
    if (e >= Ec) return;
    int c = 0;
    for (int n = 0; n < Nc; n++) {
        if (out_mask[(size_t)e * Nc + n] != 0.0f) { c = n; break; }
    }
    g_chk[e] = c;
    // Recover var[e] from the one-hot input mask (coalesced: fixed vv row across threads)
    int v = 0;
    for (int vv = 0; vv < Kv; vv++) {
        if (in_mask[(size_t)vv * Ec + e] != 0.0f) { v = vv; break; }
    }
    g_var[e] = v;
}

// ---------------- setup 2: check-node adjacency lists (edge-index order) ----------------
__global__ void k_cadj() {
    int n = blockIdx.x * blockDim.x + threadIdx.x;
    if (n >= Nc) return;
    int cnt = 0;
    for (int e = 0; e < Ec; e++) {
        if (g_chk[e] == n && cnt < MAXDEG) g_cadj[n * MAXDEG + cnt++] = e;
    }
    g_cdeg[n] = cnt;
}

// ---------------- setup 3: the two sibling edges on the same variable node ----------------
__global__ void k_sib() {
    int e = blockIdx.x * blockDim.x + threadIdx.x;
    if (e >= Ec) return;
    int v = g_var[e];
    int c = 0, s0 = e, s1 = e;
    for (int e2 = 0; e2 < Ec; e2++) {
        if (e2 != e && g_var[e2] == v) {
            if (c == 0) s0 = e2; else if (c == 1) s1 = e2;
            c++;
        }
    }
    g_sib0[e] = s0;
    g_sib1[e] = s1;
}

// ---------------- setup 4: per-edge neighbor lists + gathered weights (zero-padded) ----
__global__ void k_gather(const float* __restrict__ we1,
                         const float* __restrict__ we2,
                         const float* __restrict__ we3,
                         const float* __restrict__ w_out) {
    int e = blockIdx.x * blockDim.x + threadIdx.x;
    if (e >= Ec) return;
    int n = g_chk[e];
    int d = g_cdeg[n];
    int cnt = 0;
    for (int j = 0; j < d; j++) {
        int e2 = g_cadj[n * MAXDEG + j];
        if (e2 == e) continue;
        g_nbr[cnt * Ec + e] = e2;
        g_w1 [cnt * Ec + e] = we1[(size_t)e2 * Ec + e];
        g_w2 [cnt * Ec + e] = we2[(size_t)e2 * Ec + e];
        g_w3 [cnt * Ec + e] = we3[(size_t)e2 * Ec + e];
        cnt++;
    }
    g_nnb[e] = cnt;
    // zero-pad the tail so a branch-uniform padded loop computes the exact sum
    for (int j = cnt; j < MAXNB; j++) {
        g_nbr[j * Ec + e] = 0;
        g_w1 [j * Ec + e] = 0.0f;
        g_w2 [j * Ec + e] = 0.0f;
        g_w3 [j * Ec + e] = 0.0f;
    }
    g_wo[e] = w_out[(size_t)e * Nc + n];
}

// ---------------- fused 3-iteration BP decoder: one CTA per batch row ----------------
__device__ __forceinline__ void odd_stage(const float* __restrict__ s_lv,
                                          const float* __restrict__ s_in,
                                          const float* __restrict__ wv,
                                          const float* __restrict__ gw,
                                          float* __restrict__ s_out,
                                          int tid) {
    for (int e = tid; e < Ec; e += TPB) {
        float acc = s_lv[e] * wv[e];
        // warp-uniform trip count: all lanes run to the warp's max nn; padded
        // weights are zero so extra iterations are exact no-ops.
        int nn = g_nnb[e];
        int wmax = __reduce_max_sync(0xFFFFFFFFu, nn);
        #pragma unroll 4
        for (int j = 0; j < wmax; j++) {
            acc += s_in[g_nbr[j * Ec + e]] * gw[j * Ec + e];
        }
        acc = fminf(fmaxf(acc, -CLIPV), CLIPV);
        s_out[e] = tanhf(0.5f * acc);
    }
}

__device__ __forceinline__ void even_stage(const float* __restrict__ s_in,
                                           float* __restrict__ s_out,
                                           int tid) {
    for (int e = tid; e < Ec; e += TPB) {
        float o0 = s_in[g_sib0[e]];
        float o1 = s_in[g_sib1[e]];
        float mag = (fabsf(o0) + 1e-12f) * (fabsf(o1) + 1e-12f);
        // sign(o0)*sign(o1) via XOR of fp32 sign bits, OR'd onto |mag|
        unsigned int sbit = (__float_as_uint(o0) ^ __float_as_uint(o1)) & 0x80000000u;
        float ev = __uint_as_float(__float_as_uint(mag) | sbit);
        ev = fminf(fmaxf(ev, -1.0f + 1e-7f), 1.0f - 1e-7f);
        s_out[e] = logf((1.0f + ev) / (1.0f - ev));   // 2*artanh(ev)
    }
}

__global__ void __launch_bounds__(TPB)
k_main(const float* __restrict__ x,
       const float* __restrict__ wv1,
       const float* __restrict__ wv2,
       const float* __restrict__ wv3,
       float* __restrict__ out) {
    __shared__ float s_x [Kv];
    __shared__ float s_lv[Ec];
    __shared__ float s_a [Ec];   // odd messages
    __shared__ float s_b [Ec];   // even messages

    const int tid = threadIdx.x;
    const size_t b = blockIdx.x;

    // stage 0: load channel LLRs, broadcast to edges
    const float* xr = x + b * Kv;
    for (int i = tid; i < Kv; i += TPB) s_x[i] = xr[i];
    __syncthreads();
    for (int e = tid; e < Ec; e += TPB) s_lv[e] = s_x[g_var[e]];
    __syncthreads();

    // iteration 1
    odd_stage(s_lv, s_lv, wv1, g_w1, s_a, tid);  __syncthreads();
    even_stage(s_a, s_b, tid);                   __syncthreads();
    // iteration 2
    odd_stage(s_lv, s_b, wv2, g_w2, s_a, tid);   __syncthreads();
    even_stage(s_a, s_b, tid);                   __syncthreads();
    // iteration 3 (final odd)
    odd_stage(s_lv, s_b, wv3, g_w3, s_a, tid);   __syncthreads();

    // output layer: per check node, sum odd messages * w_out, sigmoid
    for (int n = tid; n < Nc; n += TPB) {
        float acc = 0.0f;
        int d = g_cdeg[n];
        for (int j = 0; j < d; j++) {
            int e = g_cadj[n * MAXDEG + j];
            acc += s_a[e] * g_wo[e];
        }
        out[b * Nc + n] = 1.0f / (1.0f + expf(-acc));
    }
}

// ---------------- launcher ----------------
extern "C" void kernel_launch(void* const* d_in, const int* in_sizes, int n_in,
                              void* d_out, int out_size) {
    const float* x       = (const float*)d_in[0];
    const float* in_mask = (const float*)d_in[1];
    const float* out_mask= (const float*)d_in[2];
    // d_in[3] = o2e_mask, d_in[4] = e2o_mask: structure recomputed from chk/var, never read
    const float* wv1     = (const float*)d_in[5];
    const float* we1     = (const float*)d_in[6];
    const float* wv2     = (const float*)d_in[7];
    const float* we2     = (const float*)d_in[8];
    const float* wv3     = (const float*)d_in[9];
    const float* we3     = (const float*)d_in[10];
    const float* w_out   = (const float*)d_in[11];
    float* out = (float*)d_out;

    k_struct<<<(Ec + 255) / 256, 256>>>(in_mask, out_mask);
    k_cadj  <<<(Nc + 255) / 256, 256>>>();
    k_sib   <<<(Ec + 255) / 256, 256>>>();
    k_gather<<<(Ec + 255) / 256, 256>>>(we1, we2, we3, w_out);
    k_main  <<<Bb, TPB>>>(x, wv1, wv2, wv3, out);
}

// round 5
// speedup vs baseline: 1.0363x; 1.0363x over previous
#include <cuda_runtime.h>
#include <math.h>

// Problem constants (fixed by the dataset)
#define Ec     3072   // edges = K*DV
#define Kv     1024   // variable nodes
#define Nc     512    // check nodes
#define Bb     2048   // batch
#define DV     3      // variable degree
#define MAXDEG 32     // check-degree bound (Poisson(6); P(>32) ~ 1e-15)
#define NG     (Ec/32)      // 96 warp-groups of sorted slots
#define TABCAP (MAXDEG*Ec)  // packed-table capacity bound
#define CLIPV  10.0f
#define TPB    512

// ---------------- persistent scratch (__device__ globals; no allocs) ----------------
__device__ int   g_chk[Ec], g_var[Ec];
__device__ int   g_cdeg[Nc];
__device__ int   g_cadj[Nc * MAXDEG];
__device__ int   g_vlist[Kv * DV];
__device__ int   g_nn[Ec];
__device__ int   g_perm[Ec], g_inv[Ec];
__device__ int   g_varp[Ec];
__device__ int2  g_sibp[Ec];            // {sib0_slot, sib1_slot}
__device__ int   g_gbase[NG], g_gtrip[NG];
__device__ int2  g_tab1[TABCAP], g_tab2[TABCAP], g_tab3[TABCAP];  // {nbr_slot, w_bits}
__device__ float g_wv1p[Ec], g_wv2p[Ec], g_wv3p[Ec];
__device__ int2  g_otab[Nc * MAXDEG];   // {slot, w_bits}
__device__ int   g_onn[Nc];

// ---------------- kernel 1: recover chk[e], var[e] from the one-hot masks ----------------
__global__ void k_struct(const float* __restrict__ in_mask,
                         const float* __restrict__ out_mask) {
    int e = blockIdx.x * blockDim.x + threadIdx.x;
    if (e >= Ec) return;
    int c = 0;
    for (int n = 0; n < Nc; n++) {
        if (out_mask[(size_t)e * Nc + n] != 0.0f) { c = n; break; }
    }
    g_chk[e] = c;
    int v = 0;
    for (int vv = 0; vv < Kv; vv++) {          // coalesced across threads (fixed vv)
        if (in_mask[(size_t)vv * Ec + e] != 0.0f) { v = vv; break; }
    }
    g_var[e] = v;
}

// ---------------- kernel 2 (single block): adjacency, degree sort, packed tables ------
__global__ void __launch_bounds__(1024)
k_setupB(const float* __restrict__ we1,
         const float* __restrict__ we2,
         const float* __restrict__ we3,
         const float* __restrict__ w_out,
         const float* __restrict__ wv1,
         const float* __restrict__ wv2,
         const float* __restrict__ wv3) {
    const int t = threadIdx.x;

    // A: check adjacency lists + var lists (scan-based, deterministic order)
    if (t < Nc) {
        int cnt = 0;
        for (int e = 0; e < Ec; e++)
            if (g_chk[e] == t && cnt < MAXDEG) g_cadj[t * MAXDEG + cnt++] = e;
        g_cdeg[t] = cnt;
    }
    if (t < Kv) {
        int cnt = 0;
        for (int e = 0; e < Ec; e++)
            if (g_var[e] == t && cnt < DV) g_vlist[t * DV + cnt++] = e;
    }
    __syncthreads();

    // B: neighbor count per edge + counting sort (ascending by nn)
    __shared__ int hist[MAXDEG + 1];
    __shared__ int off [MAXDEG + 1];
    if (t <= MAXDEG) hist[t] = 0;
    __syncthreads();
    for (int e = t; e < Ec; e += 1024) {
        int nn = g_cdeg[g_chk[e]] - 1;
        if (nn < 0) nn = 0;
        g_nn[e] = nn;
        atomicAdd(&hist[nn], 1);
    }
    __syncthreads();
    if (t == 0) {
        int acc = 0;
        for (int d = 0; d <= MAXDEG; d++) { off[d] = acc; acc += hist[d]; }
    }
    __syncthreads();
    for (int e = t; e < Ec; e += 1024) {
        int pos = atomicAdd(&off[g_nn[e]], 1);
        g_perm[pos] = e;
        g_inv[e]    = pos;
    }
    __syncthreads();

    // C: per-group trip count (sorted ascending -> last slot holds group max) + bases
    if (t < NG) g_gtrip[t] = g_nn[g_perm[t * 32 + 31]];
    __syncthreads();
    if (t == 0) {
        int base = 0;
        for (int g = 0; g < NG; g++) { g_gbase[g] = base; base += 32 * g_gtrip[g]; }
    }
    __syncthreads();

    // D: per-slot gathered data in sorted slot space
    for (int slot = t; slot < Ec; slot += 1024) {
        int e = g_perm[slot];
        int n = g_chk[e];
        int v = g_var[e];
        g_varp[slot]  = v;
        g_wv1p[slot]  = wv1[e];
        g_wv2p[slot]  = wv2[e];
        g_wv3p[slot]  = wv3[e];
        // siblings on the same variable node (DV=3 -> exactly two others)
        int a = g_vlist[v * DV], b = g_vlist[v * DV + 1], c = g_vlist[v * DV + 2];
        int s0, s1;
        if (e == a)      { s0 = b; s1 = c; }
        else if (e == b) { s0 = a; s1 = c; }
        else             { s0 = a; s1 = b; }
        int2 sp; sp.x = g_inv[s0]; sp.y = g_inv[s1];
        g_sibp[slot] = sp;
        // packed neighbor tables, zero-padded to the group trip
        int base = g_gbase[slot >> 5] + (slot & 31);
        int trip = g_gtrip[slot >> 5];
        int d = g_cdeg[n];
        int cnt = 0;
        for (int j = 0; j < d; j++) {
            int e2 = g_cadj[n * MAXDEG + j];
            if (e2 == e) continue;
            int2 p;
            p.x = g_inv[e2];
            p.y = __float_as_int(we1[(size_t)e2 * Ec + e]);
            g_tab1[base + cnt * 32] = p;
            p.y = __float_as_int(we2[(size_t)e2 * Ec + e]);
            g_tab2[base + cnt * 32] = p;
            p.y = __float_as_int(we3[(size_t)e2 * Ec + e]);
            g_tab3[base + cnt * 32] = p;
            cnt++;
        }
        int2 z; z.x = 0; z.y = 0;
        for (; cnt < trip; cnt++) {
            g_tab1[base + cnt * 32] = z;
            g_tab2[base + cnt * 32] = z;
            g_tab3[base + cnt * 32] = z;
        }
    }

    // E: output-layer table (slot space)
    if (t < Nc) {
        int d = g_cdeg[t];
        for (int j = 0; j < d; j++) {
            int e = g_cadj[t * MAXDEG + j];
            int2 p;
            p.x = g_inv[e];
            p.y = __float_as_int(w_out[(size_t)e * Nc + t]);
            g_otab[t * MAXDEG + j] = p;
        }
        g_onn[t] = d;
    }
}

// ---------------- fused 3-iteration BP decoder: one CTA per batch row ----------------
__device__ __forceinline__ void odd_stage(const float* __restrict__ s_lv,
                                          const float* __restrict__ s_in,
                                          const float* __restrict__ wvp,
                                          const int2*  __restrict__ tab,
                                          float* __restrict__ s_out,
                                          int tid) {
    for (int slot = tid; slot < Ec; slot += TPB) {
        int g    = slot >> 5;
        int base = g_gbase[g] + (slot & 31);   // warp-uniform g -> broadcast loads
        int trip = g_gtrip[g];
        float acc = s_lv[slot] * wvp[slot];
        #pragma unroll 2
        for (int j = 0; j < trip; j++) {
            int2 p = tab[base + (j << 5)];     // one coalesced 8B load
            acc = fmaf(s_in[p.x], __int_as_float(p.y), acc);
        }
        acc = fminf(fmaxf(acc, -CLIPV), CLIPV);
        float tq = __expf(acc);                // tanh(acc/2) = (e^a - 1)/(e^a + 1)
        s_out[slot] = __fdividef(tq - 1.0f, tq + 1.0f);
    }
}

__device__ __forceinline__ void even_stage(const float* __restrict__ s_in,
                                           float* __restrict__ s_out,
                                           int tid) {
    for (int slot = tid; slot < Ec; slot += TPB) {
        int2 sp = g_sibp[slot];                // one coalesced 8B load
        float o0 = s_in[sp.x];
        float o1 = s_in[sp.y];
        float mag = (fabsf(o0) + 1e-12f) * (fabsf(o1) + 1e-12f);
        unsigned int sbit = (__float_as_uint(o0) ^ __float_as_uint(o1)) & 0x80000000u;
        float ev = __uint_as_float(__float_as_uint(mag) | sbit);
        ev = fminf(fmaxf(ev, -1.0f + 1e-7f), 1.0f - 1e-7f);
        s_out[slot] = __logf(__fdividef(1.0f + ev, 1.0f - ev));   // 2*artanh(ev)
    }
}

__global__ void __launch_bounds__(TPB)
k_main(const float* __restrict__ x, float* __restrict__ out) {
    __shared__ float s_x [Kv];
    __shared__ float s_lv[Ec];
    __shared__ float s_a [Ec];
    __shared__ float s_b [Ec];

    const int tid = threadIdx.x;
    const size_t b = blockIdx.x;

    const float* xr = x + b * Kv;
    for (int i = tid; i < Kv; i += TPB) s_x[i] = xr[i];
    __syncthreads();
    for (int slot = tid; slot < Ec; slot += TPB) s_lv[slot] = s_x[g_varp[slot]];
    __syncthreads();

    odd_stage (s_lv, s_lv, g_wv1p, g_tab1, s_a, tid);  __syncthreads();
    even_stage(s_a, s_b, tid);                         __syncthreads();
    odd_stage (s_lv, s_b, g_wv2p, g_tab2, s_a, tid);   __syncthreads();
    even_stage(s_a, s_b, tid);                         __syncthreads();
    odd_stage (s_lv, s_b, g_wv3p, g_tab3, s_a, tid);   __syncthreads();

    for (int n = tid; n < Nc; n += TPB) {
        float acc = 0.0f;
        int d = g_onn[n];
        for (int j = 0; j < d; j++) {
            int2 p = g_otab[n * MAXDEG + j];
            acc = fmaf(s_a[p.x], __int_as_float(p.y), acc);
        }
        out[b * Nc + n] = __fdividef(1.0f, 1.0f + __expf(-acc));
    }
}

// ---------------- launcher (3 kernels -> ncu -s 5 -c 1 captures k_main) ----------------
extern "C" void kernel_launch(void* const* d_in, const int* in_sizes, int n_in,
                              void* d_out, int out_size) {
    const float* x       = (const float*)d_in[0];
    const float* in_mask = (const float*)d_in[1];
    const float* out_mask= (const float*)d_in[2];
    // d_in[3]=o2e_mask, d_in[4]=e2o_mask: structure recomputed from chk/var, never read
    const float* wv1     = (const float*)d_in[5];
    const float* we1     = (const float*)d_in[6];
    const float* wv2     = (const float*)d_in[7];
    const float* we2     = (const float*)d_in[8];
    const float* wv3     = (const float*)d_in[9];
    const float* we3     = (const float*)d_in[10];
    const float* w_out   = (const float*)d_in[11];
    float* out = (float*)d_out;

    k_struct<<<(Ec + 255) / 256, 256>>>(in_mask, out_mask);
    k_setupB<<<1, 1024>>>(we1, we2, we3, w_out, wv1, wv2, wv3);
    k_main  <<<Bb, TPB>>>(x, out);
}

// round 6
// speedup vs baseline: 1.5696x; 1.5146x over previous
#include <cuda_runtime.h>
#include <math.h>

// Problem constants (fixed by the dataset)
#define Ec     3072   // edges = K*DV
#define Kv     1024   // variable nodes
#define Nc     512    // check nodes
#define Bb     2048   // batch
#define DV     3      // variable degree
#define MAXDEG 32     // check-degree bound (Poisson(6); P(>32) ~ 1e-15)
#define NG     (Ec/32)      // 96 warp-groups of sorted slots
#define TABCAP (MAXDEG*Ec)  // packed-table capacity bound
#define CLIPV  10.0f
#define R      2            // batch rows per k_main CTA
#define TPB2   1024

// ---------------- persistent scratch (__device__ globals; no allocs) ----------------
__device__ int   g_chk[Ec], g_var[Ec];
__device__ int   g_cdeg[Nc];
__device__ int   g_cadj[Nc * MAXDEG];
__device__ int   g_vlist[Kv * DV];
__device__ int   g_nn[Ec];
__device__ int   g_perm[Ec], g_inv[Ec];
__device__ int   g_varp[Ec];
__device__ int2  g_sibp[Ec];            // {sib0_slot*R, sib1_slot*R}
__device__ int   g_gbase[NG], g_gtrip[NG];
__device__ int2  g_tab1[TABCAP], g_tab2[TABCAP], g_tab3[TABCAP];  // {nbr_slot*R, w_bits}
__device__ float g_wv1p[Ec], g_wv2p[Ec], g_wv3p[Ec];
__device__ int2  g_otab[Nc * MAXDEG];   // {slot*R, w_bits}
__device__ int   g_onn[Nc];

// ---------------- kernel 1: element-parallel one-hot recovery (was 505us serial) -----
__global__ void k_struct(const float* __restrict__ in_mask,
                         const float* __restrict__ out_mask) {
    const int stride = gridDim.x * blockDim.x;
    int idx = blockIdx.x * blockDim.x + threadIdx.x;
    // in_mask is (Kv, Ec) one-hot per column -> exactly one writer per edge
    for (int i = idx; i < Kv * Ec; i += stride) {
        if (in_mask[i] != 0.0f) g_var[i % Ec] = i / Ec;
    }
    // out_mask is (Ec, Nc) one-hot per row -> exactly one writer per edge
    for (int i = idx; i < Ec * Nc; i += stride) {
        if (out_mask[i] != 0.0f) g_chk[i / Nc] = i % Nc;
    }
}

// ---------------- kernel 2 (single block): adjacency, degree sort, slot metadata ------
__global__ void __launch_bounds__(1024)
k_setupA(const float* __restrict__ w_out,
         const float* __restrict__ wv1,
         const float* __restrict__ wv2,
         const float* __restrict__ wv3) {
    const int t = threadIdx.x;

    // A: check adjacency lists + var lists (scan-based, deterministic order)
    if (t < Nc) {
        int cnt = 0;
        for (int e = 0; e < Ec; e++)
            if (g_chk[e] == t && cnt < MAXDEG) g_cadj[t * MAXDEG + cnt++] = e;
        g_cdeg[t] = cnt;
    }
    if (t < Kv) {
        int cnt = 0;
        for (int e = 0; e < Ec; e++)
            if (g_var[e] == t && cnt < DV) g_vlist[t * DV + cnt++] = e;
    }
    __syncthreads();

    // B: neighbor count per edge + counting sort (ascending by nn).
    // Atomic order only permutes slots within equal-nn buckets; per-edge FMA
    // order is fixed by cadj order -> outputs bitwise deterministic.
    __shared__ int hist[MAXDEG + 1];
    __shared__ int off [MAXDEG + 1];
    if (t <= MAXDEG) hist[t] = 0;
    __syncthreads();
    for (int e = t; e < Ec; e += 1024) {
        int nn = g_cdeg[g_chk[e]] - 1;
        if (nn < 0) nn = 0;
        g_nn[e] = nn;
        atomicAdd(&hist[nn], 1);
    }
    __syncthreads();
    if (t == 0) {
        int acc = 0;
        for (int d = 0; d <= MAXDEG; d++) { off[d] = acc; acc += hist[d]; }
    }
    __syncthreads();
    for (int e = t; e < Ec; e += 1024) {
        int pos = atomicAdd(&off[g_nn[e]], 1);
        g_perm[pos] = e;
        g_inv[e]    = pos;
    }
    __syncthreads();

    // C: per-group trip count (ascending sort -> slot 31 holds group max) + bases
    if (t < NG) g_gtrip[t] = g_nn[g_perm[t * 32 + 31]];
    __syncthreads();
    if (t == 0) {
        int base = 0;
        for (int g = 0; g < NG; g++) { g_gbase[g] = base; base += 32 * g_gtrip[g]; }
    }
    __syncthreads();

    // D: per-slot metadata in sorted slot space (indices premultiplied by R)
    for (int slot = t; slot < Ec; slot += 1024) {
        int e = g_perm[slot];
        int v = g_var[e];
        g_varp[slot] = v;
        g_wv1p[slot] = wv1[e];
        g_wv2p[slot] = wv2[e];
        g_wv3p[slot] = wv3[e];
        int a = g_vlist[v * DV], b = g_vlist[v * DV + 1], c = g_vlist[v * DV + 2];
        int s0, s1;
        if (e == a)      { s0 = b; s1 = c; }
        else if (e == b) { s0 = a; s1 = c; }
        else             { s0 = a; s1 = b; }
        int2 sp; sp.x = g_inv[s0] * R; sp.y = g_inv[s1] * R;
        g_sibp[slot] = sp;
    }

    // E: output-layer table (slot space, premultiplied)
    if (t < Nc) {
        int d = g_cdeg[t];
        for (int j = 0; j < d; j++) {
            int e = g_cadj[t * MAXDEG + j];
            int2 p;
            p.x = g_inv[e] * R;
            p.y = __float_as_int(w_out[(size_t)e * Nc + t]);
            g_otab[t * MAXDEG + j] = p;
        }
        g_onn[t] = d;
    }
}

// ---------------- kernel 3: packed weight tables (one block per sorted group) ---------
__global__ void k_tables(const float* __restrict__ we1,
                         const float* __restrict__ we2,
                         const float* __restrict__ we3) {
    const int g    = blockIdx.x;
    const int trip = g_gtrip[g];
    const int base = g_gbase[g];
    const int total = 32 * trip;
    for (int t = threadIdx.x; t < total; t += blockDim.x) {
        int lane = t & 31, j = t >> 5;
        int slot = g * 32 + lane;
        int e = g_perm[slot];
        int n = g_chk[e];
        int d = g_cdeg[n];
        // find j-th neighbor of e on check n, excluding e itself
        int e2 = -1, cnt = 0;
        for (int k = 0; k < d; k++) {
            int cand = g_cadj[n * MAXDEG + k];
            if (cand == e) continue;
            if (cnt == j) { e2 = cand; break; }
            cnt++;
        }
        int2 p1, p2, p3;
        if (e2 >= 0) {
            int nbr = g_inv[e2] * R;
            p1.x = p2.x = p3.x = nbr;
            p1.y = __float_as_int(we1[(size_t)e2 * Ec + e]);
            p2.y = __float_as_int(we2[(size_t)e2 * Ec + e]);
            p3.y = __float_as_int(we3[(size_t)e2 * Ec + e]);
        } else {
            p1.x = p1.y = 0; p2 = p1; p3 = p1;   // zero-pad: exact no-op FMA
        }
        g_tab1[base + t] = p1;
        g_tab2[base + t] = p2;
        g_tab3[base + t] = p3;
    }
}

// ---------------- fused 3-iteration BP decoder: R=2 batch rows per CTA ----------------
__device__ __forceinline__ void odd_stage(const float* __restrict__ s_lv,
                                          const float* __restrict__ s_in,
                                          const float* __restrict__ wvp,
                                          const int2*  __restrict__ tab,
                                          float* __restrict__ s_out,
                                          int tid) {
    for (int slot = tid; slot < Ec; slot += TPB2) {
        int g    = slot >> 5;
        int base = g_gbase[g] + (slot & 31);   // warp-uniform g -> broadcast loads
        int trip = g_gtrip[g];
        float wv = wvp[slot];
        float2 lv = ((const float2*)s_lv)[slot];
        float a0 = lv.x * wv, a1 = lv.y * wv;
        #pragma unroll 2
        for (int j = 0; j < trip; j++) {
            int2 p = tab[base + (j << 5)];               // one coalesced 8B load
            float w = __int_as_float(p.y);
            float2 m = *(const float2*)(s_in + p.x);     // both rows, one LDS.64
            a0 = fmaf(m.x, w, a0);
            a1 = fmaf(m.y, w, a1);
        }
        a0 = fminf(fmaxf(a0, -CLIPV), CLIPV);
        a1 = fminf(fmaxf(a1, -CLIPV), CLIPV);
        float t0 = __expf(a0), t1 = __expf(a1);          // tanh(a/2) = (e^a-1)/(e^a+1)
        float2 r;
        r.x = __fdividef(t0 - 1.0f, t0 + 1.0f);
        r.y = __fdividef(t1 - 1.0f, t1 + 1.0f);
        ((float2*)s_out)[slot] = r;
    }
}

__device__ __forceinline__ float artanh2(float o0, float o1) {
    float mag = (fabsf(o0) + 1e-12f) * (fabsf(o1) + 1e-12f);
    unsigned int sbit = (__float_as_uint(o0) ^ __float_as_uint(o1)) & 0x80000000u;
    float ev = __uint_as_float(__float_as_uint(mag) | sbit);
    ev = fminf(fmaxf(ev, -1.0f + 1e-7f), 1.0f - 1e-7f);
    return __logf(__fdividef(1.0f + ev, 1.0f - ev));     // 2*artanh(ev)
}

__device__ __forceinline__ void even_stage(const float* __restrict__ s_in,
                                           float* __restrict__ s_out,
                                           int tid) {
    for (int slot = tid; slot < Ec; slot += TPB2) {
        int2 sp = g_sibp[slot];
        float2 o0 = *(const float2*)(s_in + sp.x);
        float2 o1 = *(const float2*)(s_in + sp.y);
        float2 r;
        r.x = artanh2(o0.x, o1.x);
        r.y = artanh2(o0.y, o1.y);
        ((float2*)s_out)[slot] = r;
    }
}

__global__ void __launch_bounds__(TPB2)
k_main(const float* __restrict__ x, float* __restrict__ out) {
    extern __shared__ float smem[];
    float* s_lv = smem;                 // [Ec][R]
    float* s_a  = smem + Ec * R;        // [Ec][R]
    float* s_b  = smem + 2 * Ec * R;    // [Ec][R]
    float* s_x  = smem + 3 * Ec * R;    // [R][Kv]

    const int tid = threadIdx.x;
    const int b0  = blockIdx.x * R;

    // load R contiguous batch rows of x (coalesced float4 copy)
    const float4* xr = (const float4*)(x + (size_t)b0 * Kv);
    float4* sx4 = (float4*)s_x;
    for (int i = tid; i < R * Kv / 4; i += TPB2) sx4[i] = xr[i];
    __syncthreads();
    // broadcast LLRs to edge slots, row-interleaved
    for (int slot = tid; slot < Ec; slot += TPB2) {
        int v = g_varp[slot];
        float2 q; q.x = s_x[v]; q.y = s_x[Kv + v];
        ((float2*)s_lv)[slot] = q;
    }
    __syncthreads();

    odd_stage (s_lv, s_lv, g_wv1p, g_tab1, s_a, tid);  __syncthreads();
    even_stage(s_a, s_b, tid);                         __syncthreads();
    odd_stage (s_lv, s_b, g_wv2p, g_tab2, s_a, tid);   __syncthreads();
    even_stage(s_a, s_b, tid);                         __syncthreads();
    odd_stage (s_lv, s_b, g_wv3p, g_tab3, s_a, tid);   __syncthreads();

    // output: Nc*R = 1024 = TPB2 -> one item per thread, coalesced row-major writes
    {
        int r = tid / Nc;          // 0..R-1
        int n = tid % Nc;
        float acc = 0.0f;
        int d = g_onn[n];
        for (int j = 0; j < d; j++) {
            int2 p = g_otab[n * MAXDEG + j];
            acc = fmaf(s_a[p.x + r], __int_as_float(p.y), acc);
        }
        out[(size_t)(b0 + r) * Nc + n] = __fdividef(1.0f, 1.0f + __expf(-acc));
    }
}

// ---------------- launcher ----------------
extern "C" void kernel_launch(void* const* d_in, const int* in_sizes, int n_in,
                              void* d_out, int out_size) {
    const float* x       = (const float*)d_in[0];
    const float* in_mask = (const float*)d_in[1];
    const float* out_mask= (const float*)d_in[2];
    // d_in[3]=o2e_mask, d_in[4]=e2o_mask: structure recomputed from chk/var, never read
    const float* wv1     = (const float*)d_in[5];
    const float* we1     = (const float*)d_in[6];
    const float* wv2     = (const float*)d_in[7];
    const float* we2     = (const float*)d_in[8];
    const float* wv3     = (const float*)d_in[9];
    const float* we3     = (const float*)d_in[10];
    const float* w_out   = (const float*)d_in[11];
    float* out = (float*)d_out;

    const int SMEM_MAIN = (3 * Ec * R + R * Kv) * (int)sizeof(float);  // 80 KB
    cudaFuncSetAttribute(k_main, cudaFuncAttributeMaxDynamicSharedMemorySize, SMEM_MAIN);

    k_struct<<<2368, 256>>>(in_mask, out_mask);
    k_setupA<<<1, 1024>>>(w_out, wv1, wv2, wv3);
    k_tables<<<NG, 256>>>(we1, we2, we3);
    k_main  <<<Bb / R, TPB2, SMEM_MAIN>>>(x, out);
}

// round 9
// speedup vs baseline: 4.7847x; 3.0484x over previous
#include <cuda_runtime.h>
#include <math.h>

// Problem constants (fixed by the dataset)
#define Ec     3072   // edges = K*DV
#define Kv     1024   // variable nodes
#define Nc     512    // check nodes
#define Bb     2048   // batch
#define DV     3      // variable degree
#define MAXDEG 32     // check-degree bound (Poisson(6); P(>32) ~ 1e-15)
#define NG     (Ec/32)      // 96 warp-groups of sorted slots
#define TABCAP (MAXDEG*Ec)  // packed-table capacity bound
#define CLIPV  10.0f
#define R      2            // batch rows per k_main CTA
#define TPB2   1024

// ---------------- persistent scratch (__device__ globals; no allocs) ----------------
__device__ int   g_chk[Ec], g_var[Ec];
__device__ int   g_cdeg[Nc];
__device__ int   g_vcnt[Kv];
__device__ int   g_cadj[Nc * MAXDEG];
__device__ int   g_vlist[Kv * DV];
__device__ int   g_nn[Ec];
__device__ int   g_perm[Ec], g_inv[Ec];
__device__ int   g_varp[Ec];
__device__ int2  g_sibp[Ec];            // {sib0_slot*R, sib1_slot*R}
__device__ int   g_gbase[NG], g_gtrip[NG];
__device__ int2  g_tab1[TABCAP], g_tab2[TABCAP], g_tab3[TABCAP];  // {nbr_slot*R, w_bits}
__device__ float g_wv1p[Ec], g_wv2p[Ec], g_wv3p[Ec];
__device__ int2  g_otab[Nc * MAXDEG];   // {slot*R, w_bits}
__device__ int   g_onn[Nc];

// ---------------- kernel 1: element-parallel one-hot recovery (float4 stream) --------
__global__ void k_struct(const float4* __restrict__ in_mask4,
                         const float4* __restrict__ out_mask4) {
    const int stride = gridDim.x * blockDim.x;
    int idx = blockIdx.x * blockDim.x + threadIdx.x;
    // in_mask is (Kv, Ec) one-hot per column -> exactly one writer per edge
    for (int i = idx; i < Kv * Ec / 4; i += stride) {
        float4 m = in_mask4[i];
        if (m.x != 0.0f || m.y != 0.0f || m.z != 0.0f || m.w != 0.0f) {
            int base = i * 4;
            if (m.x != 0.0f) g_var[(base    ) % Ec] = (base    ) / Ec;
            if (m.y != 0.0f) g_var[(base + 1) % Ec] = (base + 1) / Ec;
            if (m.z != 0.0f) g_var[(base + 2) % Ec] = (base + 2) / Ec;
            if (m.w != 0.0f) g_var[(base + 3) % Ec] = (base + 3) / Ec;
        }
    }
    // out_mask is (Ec, Nc) one-hot per row -> exactly one writer per edge
    for (int i = idx; i < Ec * Nc / 4; i += stride) {
        float4 m = out_mask4[i];
        if (m.x != 0.0f || m.y != 0.0f || m.z != 0.0f || m.w != 0.0f) {
            int base = i * 4;
            if (m.x != 0.0f) g_chk[(base    ) / Nc] = (base    ) % Nc;
            if (m.y != 0.0f) g_chk[(base + 1) / Nc] = (base + 1) % Nc;
            if (m.z != 0.0f) g_chk[(base + 2) / Nc] = (base + 2) % Nc;
            if (m.w != 0.0f) g_chk[(base + 3) / Nc] = (base + 3) % Nc;
        }
    }
}

// ---------------- kernel 2 (single block): adjacency via atomics+sort, degree sort ----
__global__ void __launch_bounds__(1024)
k_setupA(const float* __restrict__ w_out,
         const float* __restrict__ wv1,
         const float* __restrict__ wv2,
         const float* __restrict__ wv3) {
    const int t = threadIdx.x;

    // A: adjacency lists via atomics (parallel), then per-node insertion sort to
    // restore ascending edge order -> bitwise-deterministic downstream tables.
    if (t < Nc) g_cdeg[t] = 0;
    if (t < Kv) g_vcnt[t] = 0;
    __syncthreads();
    for (int e = t; e < Ec; e += 1024) {
        int n = g_chk[e];
        int pos = atomicAdd(&g_cdeg[n], 1);
        if (pos < MAXDEG) g_cadj[n * MAXDEG + pos] = e;
        int v = g_var[e];
        int vp = atomicAdd(&g_vcnt[v], 1);
        if (vp < DV) g_vlist[v * DV + vp] = e;
    }
    __syncthreads();
    if (t < Nc) {
        int d = g_cdeg[t];
        if (d > MAXDEG) { d = MAXDEG; g_cdeg[t] = MAXDEG; }
        int* a = g_cadj + t * MAXDEG;
        for (int i = 1; i < d; i++) {            // insertion sort ascending
            int key = a[i], j = i - 1;
            while (j >= 0 && a[j] > key) { a[j + 1] = a[j]; j--; }
            a[j + 1] = key;
        }
    }
    if (t < Kv) {
        int* a = g_vlist + t * DV;               // sort 3 ascending
        int x0 = a[0], x1 = a[1], x2 = a[2];
        int lo = min(x0, min(x1, x2));
        int hi = max(x0, max(x1, x2));
        a[0] = lo; a[1] = x0 + x1 + x2 - lo - hi; a[2] = hi;
    }
    __syncthreads();

    // B: neighbor count per edge + counting sort (ascending by nn).
    __shared__ int hist[MAXDEG + 1];
    __shared__ int off [MAXDEG + 1];
    if (t <= MAXDEG) hist[t] = 0;
    __syncthreads();
    for (int e = t; e < Ec; e += 1024) {
        int nn = g_cdeg[g_chk[e]] - 1;
        if (nn < 0) nn = 0;
        g_nn[e] = nn;
        atomicAdd(&hist[nn], 1);
    }
    __syncthreads();
    if (t == 0) {
        int acc = 0;
        for (int d = 0; d <= MAXDEG; d++) { off[d] = acc; acc += hist[d]; }
    }
    __syncthreads();
    for (int e = t; e < Ec; e += 1024) {
        int pos = atomicAdd(&off[g_nn[e]], 1);
        g_perm[pos] = e;
        g_inv[e]    = pos;
    }
    __syncthreads();

    // C: per-group trip count (ascending sort -> slot 31 holds group max) + bases
    if (t < NG) g_gtrip[t] = g_nn[g_perm[t * 32 + 31]];
    __syncthreads();
    if (t == 0) {
        int base = 0;
        for (int g = 0; g < NG; g++) { g_gbase[g] = base; base += 32 * g_gtrip[g]; }
    }
    __syncthreads();

    // D: per-slot metadata in sorted slot space (indices premultiplied by R)
    for (int slot = t; slot < Ec; slot += 1024) {
        int e = g_perm[slot];
        int v = g_var[e];
        g_varp[slot] = v;
        g_wv1p[slot] = wv1[e];
        g_wv2p[slot] = wv2[e];
        g_wv3p[slot] = wv3[e];
        int a = g_vlist[v * DV], b = g_vlist[v * DV + 1], c = g_vlist[v * DV + 2];
        int s0, s1;
        if (e == a)      { s0 = b; s1 = c; }
        else if (e == b) { s0 = a; s1 = c; }
        else             { s0 = a; s1 = b; }
        int2 sp; sp.x = g_inv[s0] * R; sp.y = g_inv[s1] * R;
        g_sibp[slot] = sp;
    }

    // E: output-layer table (slot space, premultiplied)
    if (t < Nc) {
        int d = g_cdeg[t];
        for (int j = 0; j < d; j++) {
            int e = g_cadj[t * MAXDEG + j];
            int2 p;
            p.x = g_inv[e] * R;
            p.y = __float_as_int(w_out[(size_t)e * Nc + t]);
            g_otab[t * MAXDEG + j] = p;
        }
        g_onn[t] = d;
    }
}

// ---------------- kernel 3: packed weight tables (one block per sorted group) ---------
__global__ void k_tables(const float* __restrict__ we1,
                         const float* __restrict__ we2,
                         const float* __restrict__ we3) {
    const int g    = blockIdx.x;
    const int trip = g_gtrip[g];
    const int base = g_gbase[g];
    const int total = 32 * trip;
    for (int t = threadIdx.x; t < total; t += blockDim.x) {
        int lane = t & 31, j = t >> 5;
        int slot = g * 32 + lane;
        int e = g_perm[slot];
        int n = g_chk[e];
        int d = g_cdeg[n];
        // find j-th neighbor of e on check n, excluding e itself
        int e2 = -1, cnt = 0;
        for (int k = 0; k < d; k++) {
            int cand = g_cadj[n * MAXDEG + k];
            if (cand == e) continue;
            if (cnt == j) { e2 = cand; break; }
            cnt++;
        }
        int2 p1, p2, p3;
        if (e2 >= 0) {
            int nbr = g_inv[e2] * R;
            p1.x = p2.x = p3.x = nbr;
            p1.y = __float_as_int(we1[(size_t)e2 * Ec + e]);
            p2.y = __float_as_int(we2[(size_t)e2 * Ec + e]);
            p3.y = __float_as_int(we3[(size_t)e2 * Ec + e]);
        } else {
            p1.x = p1.y = 0; p2 = p1; p3 = p1;   // zero-pad: exact no-op FMA
        }
        g_tab1[base + t] = p1;
        g_tab2[base + t] = p2;
        g_tab3[base + t] = p3;
    }
}

// ---------------- fused 3-iteration BP decoder: R=2 batch rows per CTA ----------------
__device__ __forceinline__ void odd_stage(const float* __restrict__ s_lv,
                                          const float* __restrict__ s_in,
                                          const float* __restrict__ wvp,
                                          const int2*  __restrict__ tab,
                                          float* __restrict__ s_out,
                                          int tid) {
    for (int slot = tid; slot < Ec; slot += TPB2) {
        int g    = slot >> 5;
        int base = g_gbase[g] + (slot & 31);   // warp-uniform g -> broadcast loads
        int trip = g_gtrip[g];
        float wv = wvp[slot];
        float2 lv = ((const float2*)s_lv)[slot];
        float a0 = lv.x * wv, a1 = lv.y * wv;
        #pragma unroll 2
        for (int j = 0; j < trip; j++) {
            int2 p = tab[base + (j << 5)];               // one coalesced 8B load
            float w = __int_as_float(p.y);
            float2 m = *(const float2*)(s_in + p.x);     // both rows, one LDS.64
            a0 = fmaf(m.x, w, a0);
            a1 = fmaf(m.y, w, a1);
        }
        a0 = fminf(fmaxf(a0, -CLIPV), CLIPV);
        a1 = fminf(fmaxf(a1, -CLIPV), CLIPV);
        float t0 = __expf(a0), t1 = __expf(a1);          // tanh(a/2) = (e^a-1)/(e^a+1)
        float2 r;
        r.x = __fdividef(t0 - 1.0f, t0 + 1.0f);
        r.y = __fdividef(t1 - 1.0f, t1 + 1.0f);
        ((float2*)s_out)[slot] = r;
    }
}

__device__ __forceinline__ float artanh2(float o0, float o1) {
    float mag = (fabsf(o0) + 1e-12f) * (fabsf(o1) + 1e-12f);
    unsigned int sbit = (__float_as_uint(o0) ^ __float_as_uint(o1)) & 0x80000000u;
    float ev = __uint_as_float(__float_as_uint(mag) | sbit);
    ev = fminf(fmaxf(ev, -1.0f + 1e-7f), 1.0f - 1e-7f);
    return __logf(__fdividef(1.0f + ev, 1.0f - ev));     // 2*artanh(ev)
}

__device__ __forceinline__ void even_stage(const float* __restrict__ s_in,
                                           float* __restrict__ s_out,
                                           int tid) {
    for (int slot = tid; slot < Ec; slot += TPB2) {
        int2 sp = g_sibp[slot];
        float2 o0 = *(const float2*)(s_in + sp.x);
        float2 o1 = *(const float2*)(s_in + sp.y);
        float2 r;
        r.x = artanh2(o0.x, o1.x);
        r.y = artanh2(o0.y, o1.y);
        ((float2*)s_out)[slot] = r;
    }
}

__global__ void __launch_bounds__(TPB2)
k_main(const float* __restrict__ x, float* __restrict__ out) {
    extern __shared__ float smem[];
    float* s_lv = smem;                 // [Ec][R]
    float* s_a  = smem + Ec * R;        // [Ec][R]
    float* s_b  = smem + 2 * Ec * R;    // [Ec][R]
    float* s_x  = smem + 3 * Ec * R;    // [R][Kv]

    const int tid = threadIdx.x;
    const int b0  = blockIdx.x * R;

    // load R contiguous batch rows of x (coalesced float4 copy)
    const float4* xr = (const float4*)(x + (size_t)b0 * Kv);
    float4* sx4 = (float4*)s_x;
    for (int i = tid; i < R * Kv / 4; i += TPB2) sx4[i] = xr[i];
    __syncthreads();
    // broadcast LLRs to edge slots, row-interleaved
    for (int slot = tid; slot < Ec; slot += TPB2) {
        int v = g_varp[slot];
        float2 q; q.x = s_x[v]; q.y = s_x[Kv + v];
        ((float2*)s_lv)[slot] = q;
    }
    __syncthreads();

    odd_stage (s_lv, s_lv, g_wv1p, g_tab1, s_a, tid);  __syncthreads();
    even_stage(s_a, s_b, tid);                         __syncthreads();
    odd_stage (s_lv, s_b, g_wv2p, g_tab2, s_a, tid);   __syncthreads();
    even_stage(s_a, s_b, tid);                         __syncthreads();
    odd_stage (s_lv, s_b, g_wv3p, g_tab3, s_a, tid);   __syncthreads();

    // output: Nc*R = 1024 = TPB2 -> one item per thread, coalesced row-major writes
    {
        int r = tid / Nc;          // 0..R-1
        int n = tid % Nc;
        float acc = 0.0f;
        int d = g_onn[n];
        for (int j = 0; j < d; j++) {
            int2 p = g_otab[n * MAXDEG + j];
            acc = fmaf(s_a[p.x + r], __int_as_float(p.y), acc);
        }
        out[(size_t)(b0 + r) * Nc + n] = __fdividef(1.0f, 1.0f + __expf(-acc));
    }
}

// ---------------- launcher ----------------
extern "C" void kernel_launch(void* const* d_in, const int* in_sizes, int n_in,
                              void* d_out, int out_size) {
    const float* x       = (const float*)d_in[0];
    const float* in_mask = (const float*)d_in[1];
    const float* out_mask= (const float*)d_in[2];
    // d_in[3]=o2e_mask, d_in[4]=e2o_mask: structure recomputed from chk/var, never read
    const float* wv1     = (const float*)d_in[5];
    const float* we1     = (const float*)d_in[6];
    const float* wv2     = (const float*)d_in[7];
    const float* we2     = (const float*)d_in[8];
    const float* wv3     = (const float*)d_in[9];
    const float* we3     = (const float*)d_in[10];
    const float* w_out   = (const float*)d_in[11];
    float* out = (float*)d_out;

    const int SMEM_MAIN = (3 * Ec * R + R * Kv) * (int)sizeof(float);  // 80 KB
    cudaFuncSetAttribute(k_main, cudaFuncAttributeMaxDynamicSharedMemorySize, SMEM_MAIN);

    k_struct<<<592, 256>>>((const float4*)in_mask, (const float4*)out_mask);
    k_setupA<<<1, 1024>>>(w_out, wv1, wv2, wv3);
    k_tables<<<NG, 256>>>(we1, we2, we3);
    k_main  <<<Bb / R, TPB2, SMEM_MAIN>>>(x, out);
}

// round 12
// speedup vs baseline: 5.5369x; 1.1572x over previous
#include <cuda_runtime.h>
#include <math.h>

// Problem constants (fixed by the dataset)
#define Ec     3072   // edges = K*DV
#define Kv     1024   // variable nodes
#define Nc     512    // check nodes
#define Bb     2048   // batch
#define DV     3      // variable degree
#define MAXDEG 32     // check-degree bound (Poisson(6); P(>32) ~ 1e-15)
#define NG     (Ec/32)      // 96 warp-groups of sorted slots
#define TABCAP (MAXDEG*Ec)  // packed-table capacity bound
#define CLIPV  10.0f
#define R      4            // batch rows per k_main CTA
#define TPB2   1024

// ---------------- persistent scratch (__device__ globals; no allocs) ----------------
__device__ int   g_chk[Ec], g_var[Ec];
__device__ int   g_cdeg[Nc];
__device__ int   g_vcnt[Kv];
__device__ int   g_cadj[Nc * MAXDEG];
__device__ int   g_vlist[Kv * DV];
__device__ int   g_nn[Ec];
__device__ int   g_perm[Ec], g_inv[Ec];
__device__ int2  g_vw1[Ec], g_vw2[Ec], g_vw3[Ec];  // {v*R, wv_bits} per slot
__device__ int4  g_vslt[Kv];                        // 3 edge slots of var (*R)
__device__ int   g_gbase[NG], g_gtrip[NG];
__device__ int2  g_tab1[TABCAP], g_tab2[TABCAP], g_tab3[TABCAP];  // {nbr_slot*R, w_bits}
__device__ int2  g_otab[Nc * MAXDEG];   // {slot*R, w_bits}
__device__ int   g_onn[Nc];

// ---------------- kernel 1: element-parallel one-hot recovery (float4 stream) --------
__global__ void k_struct(const float4* __restrict__ in_mask4,
                         const float4* __restrict__ out_mask4) {
    const int stride = gridDim.x * blockDim.x;
    int idx = blockIdx.x * blockDim.x + threadIdx.x;
    // in_mask is (Kv, Ec) one-hot per column -> exactly one writer per edge
    for (int i = idx; i < Kv * Ec / 4; i += stride) {
        float4 m = in_mask4[i];
        if (m.x != 0.0f || m.y != 0.0f || m.z != 0.0f || m.w != 0.0f) {
            int base = i * 4;
            if (m.x != 0.0f) g_var[(base    ) % Ec] = (base    ) / Ec;
            if (m.y != 0.0f) g_var[(base + 1) % Ec] = (base + 1) / Ec;
            if (m.z != 0.0f) g_var[(base + 2) % Ec] = (base + 2) / Ec;
            if (m.w != 0.0f) g_var[(base + 3) % Ec] = (base + 3) / Ec;
        }
    }
    // out_mask is (Ec, Nc) one-hot per row -> exactly one writer per edge
    for (int i = idx; i < Ec * Nc / 4; i += stride) {
        float4 m = out_mask4[i];
        if (m.x != 0.0f || m.y != 0.0f || m.z != 0.0f || m.w != 0.0f) {
            int base = i * 4;
            if (m.x != 0.0f) g_chk[(base    ) / Nc] = (base    ) % Nc;
            if (m.y != 0.0f) g_chk[(base + 1) / Nc] = (base + 1) % Nc;
            if (m.z != 0.0f) g_chk[(base + 2) / Nc] = (base + 2) % Nc;
            if (m.w != 0.0f) g_chk[(base + 3) / Nc] = (base + 3) % Nc;
        }
    }
}

// ---------------- kernel 2 (single block): adjacency via atomics+sort, degree sort ----
__global__ void __launch_bounds__(1024)
k_setupA(const float* __restrict__ w_out,
         const float* __restrict__ wv1,
         const float* __restrict__ wv2,
         const float* __restrict__ wv3) {
    const int t = threadIdx.x;

    // A: adjacency lists via atomics (parallel), then per-node insertion sort to
    // restore ascending edge order -> bitwise-deterministic downstream tables.
    if (t < Nc) g_cdeg[t] = 0;
    if (t < Kv) g_vcnt[t] = 0;
    __syncthreads();
    for (int e = t; e < Ec; e += 1024) {
        int n = g_chk[e];
        int pos = atomicAdd(&g_cdeg[n], 1);
        if (pos < MAXDEG) g_cadj[n * MAXDEG + pos] = e;
        int v = g_var[e];
        int vp = atomicAdd(&g_vcnt[v], 1);
        if (vp < DV) g_vlist[v * DV + vp] = e;
    }
    __syncthreads();
    if (t < Nc) {
        int d = g_cdeg[t];
        if (d > MAXDEG) { d = MAXDEG; g_cdeg[t] = MAXDEG; }
        int* a = g_cadj + t * MAXDEG;
        for (int i = 1; i < d; i++) {            // insertion sort ascending
            int key = a[i], j = i - 1;
            while (j >= 0 && a[j] > key) { a[j + 1] = a[j]; j--; }
            a[j + 1] = key;
        }
    }
    if (t < Kv) {
        int* a = g_vlist + t * DV;               // sort 3 ascending
        int x0 = a[0], x1 = a[1], x2 = a[2];
        int lo = min(x0, min(x1, x2));
        int hi = max(x0, max(x1, x2));
        a[0] = lo; a[1] = x0 + x1 + x2 - lo - hi; a[2] = hi;
    }
    __syncthreads();

    // B: neighbor count per edge + counting sort (ascending by nn).
    __shared__ int hist[MAXDEG + 1];
    __shared__ int off [MAXDEG + 1];
    if (t <= MAXDEG) hist[t] = 0;
    __syncthreads();
    for (int e = t; e < Ec; e += 1024) {
        int nn = g_cdeg[g_chk[e]] - 1;
        if (nn < 0) nn = 0;
        g_nn[e] = nn;
        atomicAdd(&hist[nn], 1);
    }
    __syncthreads();
    if (t == 0) {
        int acc = 0;
        for (int d = 0; d <= MAXDEG; d++) { off[d] = acc; acc += hist[d]; }
    }
    __syncthreads();
    for (int e = t; e < Ec; e += 1024) {
        int pos = atomicAdd(&off[g_nn[e]], 1);
        g_perm[pos] = e;
        g_inv[e]    = pos;
    }
    __syncthreads();

    // C: per-group trip count (ascending sort -> slot 31 holds group max) + bases
    if (t < NG) g_gtrip[t] = g_nn[g_perm[t * 32 + 31]];
    __syncthreads();
    if (t == 0) {
        int base = 0;
        for (int g = 0; g < NG; g++) { g_gbase[g] = base; base += 32 * g_gtrip[g]; }
    }
    __syncthreads();

    // D: per-slot {var*R, wv} tables + per-var slot triples (premultiplied by R)
    for (int slot = t; slot < Ec; slot += 1024) {
        int e = g_perm[slot];
        int v = g_var[e];
        int2 w;
        w.x = v * R;
        w.y = __float_as_int(wv1[e]); g_vw1[slot] = w;
        w.y = __float_as_int(wv2[e]); g_vw2[slot] = w;
        w.y = __float_as_int(wv3[e]); g_vw3[slot] = w;
    }
    if (t < Kv) {
        int4 s;
        s.x = g_inv[g_vlist[t * DV    ]] * R;
        s.y = g_inv[g_vlist[t * DV + 1]] * R;
        s.z = g_inv[g_vlist[t * DV + 2]] * R;
        s.w = 0;
        g_vslt[t] = s;
    }

    // E: output-layer table (slot space, premultiplied)
    if (t < Nc) {
        int d = g_cdeg[t];
        for (int j = 0; j < d; j++) {
            int e = g_cadj[t * MAXDEG + j];
            int2 p;
            p.x = g_inv[e] * R;
            p.y = __float_as_int(w_out[(size_t)e * Nc + t]);
            g_otab[t * MAXDEG + j] = p;
        }
        g_onn[t] = d;
    }
}

// ---------------- kernel 3: packed weight tables (one block per sorted group) ---------
__global__ void k_tables(const float* __restrict__ we1,
                         const float* __restrict__ we2,
                         const float* __restrict__ we3) {
    const int g    = blockIdx.x;
    const int trip = g_gtrip[g];
    const int base = g_gbase[g];
    const int total = 32 * trip;
    for (int t = threadIdx.x; t < total; t += blockDim.x) {
        int lane = t & 31, j = t >> 5;
        int slot = g * 32 + lane;
        int e = g_perm[slot];
        int n = g_chk[e];
        int d = g_cdeg[n];
        // find j-th neighbor of e on check n, excluding e itself
        int e2 = -1, cnt = 0;
        for (int k = 0; k < d; k++) {
            int cand = g_cadj[n * MAXDEG + k];
            if (cand == e) continue;
            if (cnt == j) { e2 = cand; break; }
            cnt++;
        }
        int2 p1, p2, p3;
        if (e2 >= 0) {
            int nbr = g_inv[e2] * R;
            p1.x = p2.x = p3.x = nbr;
            p1.y = __float_as_int(we1[(size_t)e2 * Ec + e]);
            p2.y = __float_as_int(we2[(size_t)e2 * Ec + e]);
            p3.y = __float_as_int(we3[(size_t)e2 * Ec + e]);
        } else {
            p1.x = p1.y = 0; p2 = p1; p3 = p1;   // zero-pad: exact no-op FMA
        }
        g_tab1[base + t] = p1;
        g_tab2[base + t] = p2;
        g_tab3[base + t] = p3;
    }
}

// ---------------- fused 3-iteration BP decoder: R=4 batch rows per CTA ----------------
__device__ __forceinline__ void odd_stage(const float* __restrict__ s_xT,
                                          const float* __restrict__ s_in,
                                          const int2*  __restrict__ vw,
                                          const int2*  __restrict__ tab,
                                          float* __restrict__ s_out,
                                          int tid) {
    for (int slot = tid; slot < Ec; slot += TPB2) {
        int g    = slot >> 5;
        int base = g_gbase[g] + (slot & 31);   // warp-uniform g -> broadcast loads
        int trip = g_gtrip[g];
        int2 vwp = vw[slot];
        float wv = __int_as_float(vwp.y);
        float4 xv = *(const float4*)(s_xT + vwp.x);    // lv for 4 rows (one LDS.128)
        float a0 = xv.x * wv, a1 = xv.y * wv, a2 = xv.z * wv, a3 = xv.w * wv;
        #pragma unroll 2
        for (int j = 0; j < trip; j++) {
            int2 p = tab[base + (j << 5)];             // one coalesced 8B load serves 4 rows
            float w = __int_as_float(p.y);
            float4 m = *(const float4*)(s_in + p.x);   // 4 rows, one LDS.128
            a0 = fmaf(m.x, w, a0);
            a1 = fmaf(m.y, w, a1);
            a2 = fmaf(m.z, w, a2);
            a3 = fmaf(m.w, w, a3);
        }
        a0 = fminf(fmaxf(a0, -CLIPV), CLIPV);
        a1 = fminf(fmaxf(a1, -CLIPV), CLIPV);
        a2 = fminf(fmaxf(a2, -CLIPV), CLIPV);
        a3 = fminf(fmaxf(a3, -CLIPV), CLIPV);
        float t0 = __expf(a0), t1 = __expf(a1), t2 = __expf(a2), t3 = __expf(a3);
        float4 r;                                      // tanh(a/2) = (e^a-1)/(e^a+1)
        r.x = __fdividef(t0 - 1.0f, t0 + 1.0f);
        r.y = __fdividef(t1 - 1.0f, t1 + 1.0f);
        r.z = __fdividef(t2 - 1.0f, t2 + 1.0f);
        r.w = __fdividef(t3 - 1.0f, t3 + 1.0f);
        ((float4*)s_out)[slot] = r;
    }
}

__device__ __forceinline__ float artanh2(float o0, float o1) {
    float mag = (fabsf(o0) + 1e-12f) * (fabsf(o1) + 1e-12f);
    unsigned int sbit = (__float_as_uint(o0) ^ __float_as_uint(o1)) & 0x80000000u;
    float ev = __uint_as_float(__float_as_uint(mag) | sbit);
    ev = fminf(fmaxf(ev, -1.0f + 1e-7f), 1.0f - 1e-7f);
    return __logf(__fdividef(1.0f + ev, 1.0f - ev));   // 2*artanh(ev)
}

__device__ __forceinline__ float4 artanh2v(float4 a, float4 b) {
    float4 r;
    r.x = artanh2(a.x, b.x);
    r.y = artanh2(a.y, b.y);
    r.z = artanh2(a.z, b.z);
    r.w = artanh2(a.w, b.w);
    return r;
}

// even (check->var) stage: var-centric, IN-PLACE (vars partition edges)
__device__ __forceinline__ void even_stage(float* __restrict__ M, int tid) {
    for (int v = tid; v < Kv; v += TPB2) {
        int4 sl = g_vslt[v];
        float4 t0 = *(const float4*)(M + sl.x);
        float4 t1 = *(const float4*)(M + sl.y);
        float4 t2 = *(const float4*)(M + sl.z);
        // e0 <- (t1,t2), e1 <- (t0,t2), e2 <- (t0,t1); products commutative in fp
        *(float4*)(M + sl.x) = artanh2v(t1, t2);
        *(float4*)(M + sl.y) = artanh2v(t0, t2);
        *(float4*)(M + sl.z) = artanh2v(t0, t1);
    }
}

__global__ void __launch_bounds__(TPB2)
k_main(const float* __restrict__ x, float* __restrict__ out) {
    extern __shared__ float smem[];
    float* M1   = smem;                 // [Ec][R] messages (ping)
    float* M2   = smem + Ec * R;        // [Ec][R] messages (pong)
    float* s_xT = smem + 2 * Ec * R;    // [Kv][R] transposed channel LLRs

    const int tid = threadIdx.x;
    const int b0  = blockIdx.x * R;

    // stage x transposed: s_xT[v][r]  (coalesced gmem reads, strided STS)
    for (int i = tid; i < R * Kv; i += TPB2) {
        int r = i >> 10;                // i / Kv
        int v = i & (Kv - 1);
        s_xT[(v << 2) + r] = x[(size_t)(b0 + r) * Kv + v];
    }
    __syncthreads();
    // materialize lv per slot into M1 (iteration-1 gather input)
    for (int slot = tid; slot < Ec; slot += TPB2) {
        ((float4*)M1)[slot] = *(const float4*)(s_xT + g_vw1[slot].x);
    }
    __syncthreads();

    odd_stage(s_xT, M1, g_vw1, g_tab1, M2, tid);  __syncthreads();
    even_stage(M2, tid);                          __syncthreads();
    odd_stage(s_xT, M2, g_vw2, g_tab2, M1, tid);  __syncthreads();
    even_stage(M1, tid);                          __syncthreads();
    odd_stage(s_xT, M1, g_vw3, g_tab3, M2, tid);  __syncthreads();

    // output: Nc*R = 2048 items, 2 per thread; i = r*Nc + n -> coalesced writes
    for (int i = tid; i < Nc * R; i += TPB2) {
        int r = i >> 9;                 // i / Nc
        int n = i & (Nc - 1);
        float acc = 0.0f;
        int d = g_onn[n];
        for (int j = 0; j < d; j++) {
            int2 p = g_otab[n * MAXDEG + j];
            acc = fmaf(M2[p.x + r], __int_as_float(p.y), acc);
        }
        out[(size_t)(b0 + r) * Nc + n] = __fdividef(1.0f, 1.0f + __expf(-acc));
    }
}

// ---------------- launcher ----------------
extern "C" void kernel_launch(void* const* d_in, const int* in_sizes, int n_in,
                              void* d_out, int out_size) {
    const float* x       = (const float*)d_in[0];
    const float* in_mask = (const float*)d_in[1];
    const float* out_mask= (const float*)d_in[2];
    // d_in[3]=o2e_mask, d_in[4]=e2o_mask: structure recomputed from chk/var, never read
    const float* wv1     = (const float*)d_in[5];
    const float* we1     = (const float*)d_in[6];
    const float* wv2     = (const float*)d_in[7];
    const float* we2     = (const float*)d_in[8];
    const float* wv3     = (const float*)d_in[9];
    const float* we3     = (const float*)d_in[10];
    const float* w_out   = (const float*)d_in[11];
    float* out = (float*)d_out;

    const int SMEM_MAIN = (2 * Ec * R + Kv * R) * (int)sizeof(float);  // 112 KB
    cudaFuncSetAttribute(k_main, cudaFuncAttributeMaxDynamicSharedMemorySize, SMEM_MAIN);

    k_struct<<<592, 256>>>((const float4*)in_mask, (const float4*)out_mask);
    k_setupA<<<1, 1024>>>(w_out, wv1, wv2, wv3);
    k_tables<<<NG, 256>>>(we1, we2, we3);
    k_main  <<<Bb / R, TPB2, SMEM_MAIN>>>(x, out);
}